// round 15
// baseline (speedup 1.0000x reference)
#include <cuda_runtime.h>
#include <cstdint>

#define WSZ   7
#define SHF   3
#define NTOK  49
#define HW    112
#define NWIN  16
#define BATCH 32

// ---- shared memory layout (32-bit word offsets), all fragment-order ----
// XF  : [mt][ks2][kst][lane][4]  QKV A-quads          6144 words
// QSF : [mt][k8][lane][4]        S-phase Q quads      2048
// KSF : [j(stride40)][k8][tg][2] S-phase K pairs      2560
// VSF : [d(stride56)][tk8][tg][2] PV V pairs          1792
// SMSF: [w][k8][lane][4]         PV prob quads        3584 (warp-private)
// OHF : [w][s][kst][lane][4]     proj A quads         2048 (aliases SMSF)
#define XS    0
#define QS    6144
#define KS    8192
#define VS    10752
#define SMS   12544
#define BT    16128    // 507 bias table (float)
#define RSOFF 16640    // 64 ints (region ids)
#define SMEM_WORDS (16640 + 64)
#define SMEM_BYTES (SMEM_WORDS * 4)

// Weights in FRAGMENT order: [ntile][ks2][lane][4], lane=(g<<2)|tg.
__device__ uint32_t g_qkvw[36 * 6 * 32 * 4];   // qkv_w [96][288]
__device__ uint32_t g_projw[12 * 6 * 32 * 4];  // proj_w [96][96]

__device__ __forceinline__ uint32_t f2tf(float f) {
    uint32_t r;
    asm("cvt.rna.tf32.f32 %0, %1;" : "=r"(r) : "f"(f));
    return r;
}

__device__ __forceinline__ void mma8(float* c,
    uint32_t a0, uint32_t a1, uint32_t a2, uint32_t a3,
    uint32_t b0, uint32_t b1)
{
    asm volatile(
        "mma.sync.aligned.m16n8k8.row.col.f32.tf32.tf32.f32 "
        "{%0,%1,%2,%3},{%4,%5,%6,%7},{%8,%9},{%0,%1,%2,%3};\n"
        : "+f"(c[0]), "+f"(c[1]), "+f"(c[2]), "+f"(c[3])
        : "r"(a0), "r"(a1), "r"(a2), "r"(a3), "r"(b0), "r"(b1));
}

__global__ void __launch_bounds__(256) prep_kernel(
    const float* __restrict__ qkv_w, const float* __restrict__ proj_w)
{
    int i = blockIdx.x * 256 + threadIdx.x;
    if (i < 36 * 6 * 32 * 4) {
        int c   = i & 3;
        int l   = (i >> 2) & 31;
        int ks2 = (i >> 7) % 6;
        int nt  = i / 768;
        int g = l >> 2, tg = l & 3;
        int ks   = 2 * ks2 + (c >> 1);
        int brow = ks * 8 + tg + ((c & 1) ? 4 : 0);
        g_qkvw[i] = f2tf(qkv_w[brow * 288 + nt * 8 + g]);
    }
    if (i < 12 * 6 * 32 * 4) {
        int c   = i & 3;
        int l   = (i >> 2) & 31;
        int ks2 = (i >> 7) % 6;
        int nt  = i / 768;
        int g = l >> 2, tg = l & 3;
        int ks   = 2 * ks2 + (c >> 1);
        int brow = ks * 8 + tg + ((c & 1) ? 4 : 0);
        g_projw[i] = f2tf(proj_w[brow * 96 + nt * 8 + g]);
    }
}

extern __shared__ uint32_t smu[];

__global__ void __launch_bounds__(128, 3) swin_kernel(
    const float* __restrict__ x,
    const float* __restrict__ qkv_b,
    const float* __restrict__ proj_b,
    const float* __restrict__ btab,
    float* __restrict__ out)
{
    float* sm_f = (float*)smu;
    const int tid = threadIdx.x;
    const int w   = tid >> 5;
    const int l   = tid & 31;
    const int g   = l >> 2;
    const int tg  = l & 3;
    const int win = blockIdx.x;
    const int b   = win >> 8;
    const int wq  = win & 255;
    const int wy  = wq >> 4;
    const int wx  = wq & 15;
    int* rs = (int*)&smu[RSOFF];

    // ---- Phase 0a: zero XF mt=3 block (covers pad rows 49-63) ----------
    for (int i = tid; i < 1536; i += 128) smu[XS + 4608 + i] = 0u;
    __syncthreads();   // row-48 gather writes overlap the zeroed block

    // ---- Phase 0b: bias table, region ids, fragment-order X gather -----
    for (int i = tid; i < 507; i += 128) sm_f[BT + i] = btab[i];
    if (tid < NTOK) {
        int ty = tid / 7, tx = tid - 7 * ty;
        int gy = wy * 7 + ty + SHF; if (gy >= HW) gy -= HW;
        int gx = wx * 7 + tx + SHF; if (gx >= HW) gx -= HW;
        int rh = gy < 105 ? 0 : (gy < 109 ? 1 : 2);
        int rw = gx < 105 ? 0 : (gx < 109 ? 1 : 2);
        rs[tid] = 3 * rh + rw;
    }
    for (int i = tid; i < NTOK * 24; i += 128) {
        int t = i / 24, c4 = i - 24 * t;
        int ty = t / 7, tx = t - 7 * ty;
        int gy = wy * 7 + ty + SHF; if (gy >= HW) gy -= HW;
        int gx = wx * 7 + tx + SHF; if (gx >= HW) gx -= HW;
        float4 v = *(const float4*)(x + ((size_t)(b * HW + gy) * HW + gx) * 96 + c4 * 4);
        int mt = t >> 4, gg = t & 7, half = (t >> 3) & 1;
        int cb = c4 * 4;
        int ks2 = cb >> 4, cc = cb & 15;
        int kst = cc >> 3, hi = (cc & 7) >> 2;
        uint32_t* d = &smu[XS + (((mt * 6 + ks2) * 2 + kst) * 32 + gg * 4) * 4
                           + hi * 2 + half];
        d[0] = f2tf(v.x); d[4] = f2tf(v.y); d[8] = f2tf(v.z); d[12] = f2tf(v.w);
    }
    __syncthreads();

    const float SCALE = 0.17677669529663687f;
    const int i0 = 16 * w + g;
    const int i1 = i0 + 8;
    const int ic0 = (i0 < NTOK) ? i0 : 0;
    const int ic1 = (i1 < NTOK) ? i1 : 0;
    // common producer sub-offsets
    const int hi_t = (tg >= 2) ? 1 : 0;         // hi for col 2*tg
    const int tgc2 = (tg & 1) * 2;              // (2*tg)&3

    float pacc[12][4];
    #pragma unroll
    for (int n = 0; n < 12; n++)
        #pragma unroll
        for (int q = 0; q < 4; q++) pacc[n][q] = 0.f;

    for (int h = 0; h < 3; ++h) {
        // ================= QKV (per-head chunk): [64,96] @ [96,96] ========
        float acc[4][3][4];
        #pragma unroll
        for (int mt = 0; mt < 4; mt++)
            #pragma unroll
            for (int jj = 0; jj < 3; jj++)
                #pragma unroll
                for (int q = 0; q < 4; q++) acc[mt][jj][q] = 0.f;

        const uint4* wb[3];
        #pragma unroll
        for (int jj = 0; jj < 3; jj++) {
            int jt  = w * 3 + jj;
            int ntg = (jt >> 2) * 12 + h * 4 + (jt & 3);
            wb[jj] = (const uint4*)&g_qkvw[(ntg * 6 * 32 + l) * 4];
        }
        #pragma unroll
        for (int ks2 = 0; ks2 < 6; ks2++) {
            uint4 bf[3];
            #pragma unroll
            for (int jj = 0; jj < 3; jj++) bf[jj] = wb[jj][ks2 * 32];
            #pragma unroll
            for (int mt = 0; mt < 4; mt++) {
                const uint4* ap = (const uint4*)&smu[XS + ((mt * 6 + ks2) * 2 * 32 + l) * 4];
                uint4 A = ap[0];     // kstep 0
                uint4 C = ap[32];    // kstep 1
                #pragma unroll
                for (int jj = 0; jj < 3; jj++) {
                    mma8(acc[mt][jj], A.x, A.y, A.z, A.w, bf[jj].x, bf[jj].y);
                    mma8(acc[mt][jj], C.x, C.y, C.z, C.w, bf[jj].z, bf[jj].w);
                }
            }
        }
        // epilogue: +bias, scale q, scatter into fragment-order Q/K/V smem
        #pragma unroll
        for (int jj = 0; jj < 3; jj++) {
            int jt = w * 3 + jj;
            int e  = jt >> 2;
            int dl = (jt & 3) * 8 + 2 * tg;
            int gc = e * 96 + h * 32 + dl;
            float b0v = qkv_b[gc], b1v = qkv_b[gc + 1];
            #pragma unroll
            for (int mt = 0; mt < 4; mt++) {
                float v00 = acc[mt][jj][0] + b0v, v01 = acc[mt][jj][1] + b1v;
                float v10 = acc[mt][jj][2] + b0v, v11 = acc[mt][jj][3] + b1v;
                if (e == 0) {
                    uint32_t* qb = &smu[QS + ((mt * 4 + (jt & 3)) * 32 + g * 4 + tgc2) * 4
                                        + hi_t * 2];
                    qb[0] = f2tf(v00 * SCALE); qb[1] = f2tf(v10 * SCALE);
                    qb[4] = f2tf(v01 * SCALE); qb[5] = f2tf(v11 * SCALE);
                } else if (e == 1) {
                    uint32_t* kb = &smu[KS + (16 * mt + g) * 40
                                        + ((jt & 3) * 4 + tgc2) * 2 + hi_t];
                    kb[0] = f2tf(v00); kb[2] = f2tf(v01);
                    kb[320] = f2tf(v10); kb[322] = f2tf(v11);
                } else {
                    uint32_t* vb = &smu[VS + dl * 56 + (2 * mt * 4 + (g & 3)) * 2
                                        + ((g >= 4) ? 1 : 0)];
                    vb[0] = f2tf(v00); vb[56] = f2tf(v01);
                    if (mt < 3) { vb[8] = f2tf(v10); vb[64] = f2tf(v11); }
                }
            }
        }
        __syncthreads();   // (B) Q/K/V visible to all warps

        // ================= S = Q @ K^T  [64 x 56] =========================
        float sacc[7][4];
        #pragma unroll
        for (int nt = 0; nt < 7; nt++)
            #pragma unroll
            for (int q = 0; q < 4; q++) sacc[nt][q] = 0.f;
        #pragma unroll
        for (int k8 = 0; k8 < 4; k8++) {
            uint4 A = *(const uint4*)&smu[QS + ((w * 4 + k8) * 32 + l) * 4];
            #pragma unroll
            for (int nt = 0; nt < 7; nt++) {
                uint2 kv = *(const uint2*)&smu[KS + (nt * 8 + g) * 40 + (k8 * 4 + tg) * 2];
                mma8(sacc[nt], A.x, A.y, A.z, A.w, kv.x, kv.y);
            }
        }
        // === fused epilogue: bias+mask in regs, register softmax ==========
        {
            int yi0 = ic0 / 7, xi0 = ic0 - 7 * yi0;
            int yi1 = ic1 / 7, xi1 = ic1 - 7 * yi1;
            int ri0 = rs[ic0];
            int ri1 = rs[ic1];
            #pragma unroll
            for (int nt = 0; nt < 7; nt++) {
                #pragma unroll
                for (int q = 0; q < 2; q++) {
                    int j = nt * 8 + 2 * tg + q;
                    if (j >= NTOK) {
                        sacc[nt][q]     = -1e9f;
                        sacc[nt][q + 2] = -1e9f;
                    } else {
                        int yj = j / 7, xj = j - 7 * yj;
                        int rj = rs[j];
                        sacc[nt][q] += sm_f[BT + ((yi0 - yj + 6) * 13 + (xi0 - xj + 6)) * 3 + h]
                                       + ((ri0 != rj) ? -1e9f : 0.f);
                        sacc[nt][q + 2] += sm_f[BT + ((yi1 - yj + 6) * 13 + (xi1 - xj + 6)) * 3 + h]
                                           + ((ri1 != rj) ? -1e9f : 0.f);
                    }
                }
            }
            float m0 = -1e30f, m1 = -1e30f;
            #pragma unroll
            for (int nt = 0; nt < 7; nt++) {
                m0 = fmaxf(m0, fmaxf(sacc[nt][0], sacc[nt][1]));
                m1 = fmaxf(m1, fmaxf(sacc[nt][2], sacc[nt][3]));
            }
            m0 = fmaxf(m0, __shfl_xor_sync(0xffffffffu, m0, 1));
            m0 = fmaxf(m0, __shfl_xor_sync(0xffffffffu, m0, 2));
            m1 = fmaxf(m1, __shfl_xor_sync(0xffffffffu, m1, 1));
            m1 = fmaxf(m1, __shfl_xor_sync(0xffffffffu, m1, 2));
            float s0 = 0.f, s1 = 0.f;
            #pragma unroll
            for (int nt = 0; nt < 7; nt++) {
                sacc[nt][0] = __expf(sacc[nt][0] - m0);
                sacc[nt][1] = __expf(sacc[nt][1] - m0);
                sacc[nt][2] = __expf(sacc[nt][2] - m1);
                sacc[nt][3] = __expf(sacc[nt][3] - m1);
                s0 += sacc[nt][0] + sacc[nt][1];
                s1 += sacc[nt][2] + sacc[nt][3];
            }
            s0 += __shfl_xor_sync(0xffffffffu, s0, 1);
            s0 += __shfl_xor_sync(0xffffffffu, s0, 2);
            s1 += __shfl_xor_sync(0xffffffffu, s1, 1);
            s1 += __shfl_xor_sync(0xffffffffu, s1, 2);
            float inv0 = __fdividef(1.f, s0);
            float inv1 = __fdividef(1.f, s1);
            // probs -> warp-private SMSF quads
            #pragma unroll
            for (int nt = 0; nt < 7; nt++) {
                uint32_t* pb = &smu[SMS + ((w * 7 + nt) * 32 + g * 4 + tgc2) * 4
                                    + hi_t * 2];
                pb[0] = (i0 < NTOK) ? f2tf(sacc[nt][0] * inv0) : 0u;
                pb[4] = (i0 < NTOK) ? f2tf(sacc[nt][1] * inv0) : 0u;
                pb[1] = (i1 < NTOK) ? f2tf(sacc[nt][2] * inv1) : 0u;
                pb[5] = (i1 < NTOK) ? f2tf(sacc[nt][3] * inv1) : 0u;
            }
        }
        __syncwarp();   // SMSF is warp-private: producer==consumer==warp w

        // ================= O_h = P @ V  [64 x 32] =========================
        float oacc[4][4];
        #pragma unroll
        for (int nt = 0; nt < 4; nt++)
            #pragma unroll
            for (int q = 0; q < 4; q++) oacc[nt][q] = 0.f;
        #pragma unroll
        for (int k8 = 0; k8 < 7; k8++) {
            uint4 A = *(const uint4*)&smu[SMS + ((w * 7 + k8) * 32 + l) * 4];
            #pragma unroll
            for (int nt = 0; nt < 4; nt++) {
                uint2 vv = *(const uint2*)&smu[VS + (nt * 8 + g) * 56 + (k8 * 4 + tg) * 2];
                mma8(oacc[nt], A.x, A.y, A.z, A.w, vv.x, vv.y);
            }
        }
        __syncthreads();   // (C) all SMSF reads done before OHF clobbers them

        #pragma unroll
        for (int nt = 0; nt < 4; nt++) {
            uint32_t* ob = &smu[SMS + (((w * 2 + (nt >> 1)) * 2 + (nt & 1)) * 32
                                       + g * 4 + tgc2) * 4 + hi_t * 2];
            ob[0] = f2tf(oacc[nt][0]); ob[4] = f2tf(oacc[nt][1]);
            ob[1] = f2tf(oacc[nt][2]); ob[5] = f2tf(oacc[nt][3]);
        }
        __syncwarp();   // OHF warp-private

        // === proj partial (own m-tile): pacc += O_h[i0/i1,:] @ proj_w =====
        #pragma unroll
        for (int s = 0; s < 2; s++) {
            const uint4* ap4 = (const uint4*)&smu[SMS + ((w * 2 + s) * 2 * 32 + l) * 4];
            uint4 A = ap4[0], C = ap4[32];
            const uint4* pw = (const uint4*)&g_projw[(((h * 2 + s) * 32) + l) * 4];
            #pragma unroll
            for (int n = 0; n < 12; n++) {
                uint4 bf = pw[n * 6 * 32];
                mma8(pacc[n], A.x, A.y, A.z, A.w, bf.x, bf.y);
                mma8(pacc[n], C.x, C.y, C.z, C.w, bf.z, bf.w);
            }
        }
        // no barrier: next head's conflicting writes are behind sync (B)/(C)
    }  // heads

    // ================= +proj_b, scatter to rolled-back gmem ==============
    #pragma unroll
    for (int half = 0; half < 2; half++) {
        int r = half ? i1 : i0;
        if (r < NTOK) {
            int ty = r / 7, tx = r - 7 * ty;
            int gy = wy * 7 + ty + SHF; if (gy >= HW) gy -= HW;
            int gx = wx * 7 + tx + SHF; if (gx >= HW) gx -= HW;
            float* op = out + ((size_t)(b * HW + gy) * HW + gx) * 96;
            #pragma unroll
            for (int n = 0; n < 12; n++) {
                int c = n * 8 + 2 * tg;
                float2 v;
                v.x = pacc[n][2 * half]     + proj_b[c];
                v.y = pacc[n][2 * half + 1] + proj_b[c + 1];
                *(float2*)(op + c) = v;
            }
        }
    }
}

extern "C" void kernel_launch(void* const* d_in, const int* in_sizes, int n_in,
                              void* d_out, int out_size)
{
    const float* x      = (const float*)d_in[0];
    const float* qkv_w  = (const float*)d_in[1];
    const float* qkv_b  = (const float*)d_in[2];
    const float* proj_w = (const float*)d_in[3];
    const float* proj_b = (const float*)d_in[4];
    const float* btab   = (const float*)d_in[5];
    float* out = (float*)d_out;

    cudaFuncSetAttribute(swin_kernel,
                         cudaFuncAttributeMaxDynamicSharedMemorySize,
                         SMEM_BYTES);

    prep_kernel<<<108, 256>>>(qkv_w, proj_w);

    const int n_windows = BATCH * NWIN * NWIN;  // 8192
    swin_kernel<<<n_windows, 128, SMEM_BYTES>>>(
        x, qkv_b, proj_b, btab, out);
}